// round 1
// baseline (speedup 1.0000x reference)
#include <cuda_runtime.h>

// Problem constants (fixed by the reference)
#define NQ 8192
#define MK 8192
#define BB 16
#define CC 512
#define LL 64
#define HH 8
#define DD 64

// Scratch (allocation-free rule: __device__ globals)
__device__ float g_q[NQ * CC];
__device__ float g_k[MK * CC];
__device__ float g_v[MK * CC];
__device__ float g_attn[NQ * CC];
__device__ float g_aux_scratch[NQ * LL];
__device__ int   g_key_start[BB];

// ---------------------------------------------------------------------------
// key_start[b] = exclusive prefix sum of key_batch_cnt
// ---------------------------------------------------------------------------
__global__ void key_start_kernel(const int* __restrict__ key_batch_cnt) {
    if (threadIdx.x == 0) {
        int s = 0;
        for (int b = 0; b < BB; b++) { g_key_start[b] = s; s += key_batch_cnt[b]; }
    }
}

// ---------------------------------------------------------------------------
// SGEMM (NT): C[r, c] = alpha * ( sum_k A[r,k] * Bw[c,k] + bias[c] )
// A: M x K row-major, Bw: N x K row-major (weights), all K-contiguous.
// BM=BN=128, BK=16, 256 threads, 8x8 per thread. Dims assumed multiples.
// ---------------------------------------------------------------------------
__global__ void __launch_bounds__(256) sgemm_nt(
    const float* __restrict__ A, const float* __restrict__ Bw,
    const float* __restrict__ bias, float* __restrict__ C,
    int M, int N, int K, float alpha)
{
    __shared__ __align__(16) float As[16][128];
    __shared__ __align__(16) float Bs[16][128];

    const int tid = threadIdx.x;
    const int tx  = tid & 15;      // 16 thread-cols
    const int ty  = tid >> 4;      // 16 thread-rows
    const int row0 = blockIdx.y * 128;
    const int col0 = blockIdx.x * 128;

    const int lr = tid >> 2;           // 0..63
    const int lk = (tid & 3) << 2;     // 0,4,8,12

    float acc[8][8];
#pragma unroll
    for (int i = 0; i < 8; i++)
#pragma unroll
        for (int j = 0; j < 8; j++) acc[i][j] = 0.0f;

    for (int k0 = 0; k0 < K; k0 += 16) {
#pragma unroll
        for (int s = 0; s < 2; s++) {
            int r = lr + s * 64;
            float4 v = *reinterpret_cast<const float4*>(
                &A[(size_t)(row0 + r) * K + k0 + lk]);
            As[lk + 0][r] = v.x; As[lk + 1][r] = v.y;
            As[lk + 2][r] = v.z; As[lk + 3][r] = v.w;
        }
#pragma unroll
        for (int s = 0; s < 2; s++) {
            int r = lr + s * 64;
            float4 v = *reinterpret_cast<const float4*>(
                &Bw[(size_t)(col0 + r) * K + k0 + lk]);
            Bs[lk + 0][r] = v.x; Bs[lk + 1][r] = v.y;
            Bs[lk + 2][r] = v.z; Bs[lk + 3][r] = v.w;
        }
        __syncthreads();

#pragma unroll
        for (int k = 0; k < 16; k++) {
            float4 a0 = *reinterpret_cast<const float4*>(&As[k][ty * 8]);
            float4 a1 = *reinterpret_cast<const float4*>(&As[k][ty * 8 + 4]);
            float4 b0 = *reinterpret_cast<const float4*>(&Bs[k][tx * 8]);
            float4 b1 = *reinterpret_cast<const float4*>(&Bs[k][tx * 8 + 4]);
            float ar[8] = {a0.x, a0.y, a0.z, a0.w, a1.x, a1.y, a1.z, a1.w};
            float br[8] = {b0.x, b0.y, b0.z, b0.w, b1.x, b1.y, b1.z, b1.w};
#pragma unroll
            for (int i = 0; i < 8; i++)
#pragma unroll
                for (int j = 0; j < 8; j++)
                    acc[i][j] = fmaf(ar[i], br[j], acc[i][j]);
        }
        __syncthreads();
    }

    float breg[8];
#pragma unroll
    for (int j = 0; j < 8; j++) breg[j] = bias[col0 + tx * 8 + j];

#pragma unroll
    for (int i = 0; i < 8; i++) {
        size_t r = (size_t)(row0 + ty * 8 + i);
        float4 o0, o1;
        o0.x = alpha * (acc[i][0] + breg[0]);
        o0.y = alpha * (acc[i][1] + breg[1]);
        o0.z = alpha * (acc[i][2] + breg[2]);
        o0.w = alpha * (acc[i][3] + breg[3]);
        o1.x = alpha * (acc[i][4] + breg[4]);
        o1.y = alpha * (acc[i][5] + breg[5]);
        o1.z = alpha * (acc[i][6] + breg[6]);
        o1.w = alpha * (acc[i][7] + breg[7]);
        *reinterpret_cast<float4*>(&C[r * N + col0 + tx * 8])     = o0;
        *reinterpret_cast<float4*>(&C[r * N + col0 + tx * 8 + 4]) = o1;
    }
}

// ---------------------------------------------------------------------------
// Gather attention: one block (128 threads) per query.
//   scores[l,h] = q[n,h,:] . k[g(l),h,:]   (masked -> -1000)
//   softmax over l per head; aux[n,l] = mean_h w[l,h]
//   attn[n,h,d] = sum_l w[l,h] * v[g(l),h,d]
// ---------------------------------------------------------------------------
__global__ void __launch_bounds__(128) attn_kernel(
    const int* __restrict__ index_pair,
    const int* __restrict__ index_pair_batch,
    float* __restrict__ aux_out)
{
    __shared__ __align__(16) float sq[CC];
    __shared__ float sw[LL * HH];   // scores -> weights, layout [l*8 + h]
    __shared__ int   sg[LL];

    const int n = blockIdx.x;
    const int t = threadIdx.x;

    // load q row (512 floats) as float4
    *reinterpret_cast<float4*>(&sq[t * 4]) =
        *reinterpret_cast<const float4*>(&g_q[(size_t)n * CC + t * 4]);

    if (t < LL) {
        int raw = index_pair[n * LL + t];
        int b   = index_pair_batch[n];
        sg[t] = (raw >= 0) ? (raw + g_key_start[b]) : -1;
    }
    __syncthreads();

    // ---- scores: 512 (l,h) pairs, 4 per thread ----
#pragma unroll
    for (int i = 0; i < 4; i++) {
        int idx = t + 128 * i;
        int l = idx >> 3, h = idx & 7;
        int g = sg[l];
        float acc;
        if (g >= 0) {
            const float4* kr = reinterpret_cast<const float4*>(
                &g_k[(size_t)g * CC + h * DD]);
            const float4* qr = reinterpret_cast<const float4*>(&sq[h * DD]);
            acc = 0.0f;
#pragma unroll
            for (int j = 0; j < 16; j++) {
                float4 kv = kr[j]; float4 q4 = qr[j];
                acc = fmaf(kv.x, q4.x, acc);
                acc = fmaf(kv.y, q4.y, acc);
                acc = fmaf(kv.z, q4.z, acc);
                acc = fmaf(kv.w, q4.w, acc);
            }
        } else {
            acc = -1000.0f;
        }
        sw[l * 8 + h] = acc;
    }
    __syncthreads();

    // ---- softmax over l per head: 16 threads per head ----
    {
        int h = t >> 4, j = t & 15;
        float vals[4];
        float m = -1e30f;
#pragma unroll
        for (int i = 0; i < 4; i++) {
            vals[i] = sw[(j + 16 * i) * 8 + h];
            m = fmaxf(m, vals[i]);
        }
#pragma unroll
        for (int off = 8; off; off >>= 1)
            m = fmaxf(m, __shfl_xor_sync(0xffffffffu, m, off, 16));
        float s = 0.0f;
#pragma unroll
        for (int i = 0; i < 4; i++) { vals[i] = expf(vals[i] - m); s += vals[i]; }
#pragma unroll
        for (int off = 8; off; off >>= 1)
            s += __shfl_xor_sync(0xffffffffu, s, off, 16);
        float inv = 1.0f / s;
#pragma unroll
        for (int i = 0; i < 4; i++)
            sw[(j + 16 * i) * 8 + h] = vals[i] * inv;
    }
    __syncthreads();

    // ---- aux: mean over heads ----
    if (t < LL) {
        float s = 0.0f;
#pragma unroll
        for (int h = 0; h < 8; h++) s += sw[t * 8 + h];
        aux_out[(size_t)n * LL + t] = s * 0.125f;
    }

    // ---- weighted sum: 512 (h,d) outputs, 4 per thread, coalesced v reads ----
#pragma unroll
    for (int i = 0; i < 4; i++) {
        int idx = t + 128 * i;
        int h = idx >> 6, d = idx & 63;
        float acc = 0.0f;
#pragma unroll 4
        for (int l = 0; l < LL; l++) {
            int g = sg[l];
            int gg = (g >= 0) ? g : 0;   // masked weight is exactly 0 (or ref gathers row 0)
            float w = sw[l * 8 + h];
            acc = fmaf(w, g_v[(size_t)gg * CC + h * DD + d], acc);
        }
        g_attn[(size_t)n * CC + idx] = acc;
    }
}

// ---------------------------------------------------------------------------
extern "C" void kernel_launch(void* const* d_in, const int* in_sizes, int n_in,
                              void* d_out, int out_size) {
    const float* query  = (const float*)d_in[0];
    const float* key    = (const float*)d_in[1];
    const float* value  = (const float*)d_in[2];
    const float* Win    = (const float*)d_in[3];   // [3C, C]
    const float* bin    = (const float*)d_in[4];   // [3C]
    const float* Wout   = (const float*)d_in[5];   // [C, C]
    const float* bout   = (const float*)d_in[6];   // [C]
    const int*   index_pair       = (const int*)d_in[7];
    const int*   key_batch_cnt    = (const int*)d_in[9];
    const int*   index_pair_batch = (const int*)d_in[10];
    float* out = (float*)d_out;

    float *qp, *kp, *vp, *ap, *auxs;
    cudaGetSymbolAddress((void**)&qp,   g_q);
    cudaGetSymbolAddress((void**)&kp,   g_k);
    cudaGetSymbolAddress((void**)&vp,   g_v);
    cudaGetSymbolAddress((void**)&ap,   g_attn);
    cudaGetSymbolAddress((void**)&auxs, g_aux_scratch);

    // aux output goes after attn if the flat output buffer has room for both
    float* aux_out = (out_size >= NQ * CC + NQ * LL) ? (out + (size_t)NQ * CC) : auxs;

    key_start_kernel<<<1, 32>>>(key_batch_cnt);

    const float scale = 0.125f;   // HEAD_DIM^-0.5
    dim3 gproj(CC / 128, NQ / 128);
    // q = (query @ Wq^T + bq) * scale
    sgemm_nt<<<gproj, 256>>>(query, Win,                bin,           qp, NQ, CC, CC, scale);
    // k = key @ Wk^T + bk
    sgemm_nt<<<gproj, 256>>>(key,   Win + CC * CC,      bin + CC,      kp, MK, CC, CC, 1.0f);
    // v = value @ Wv^T + bv
    sgemm_nt<<<gproj, 256>>>(value, Win + 2 * CC * CC,  bin + 2 * CC,  vp, MK, CC, CC, 1.0f);

    attn_kernel<<<NQ, 128>>>(index_pair, index_pair_batch, aux_out);

    // out = attn @ out_w^T + out_b   (written straight into d_out)
    sgemm_nt<<<gproj, 256>>>(ap, Wout, bout, out, NQ, CC, CC, 1.0f);
}

// round 2
// speedup vs baseline: 1.6784x; 1.6784x over previous
#include <cuda_runtime.h>

#define NQ 8192
#define MK 8192
#define BB 16
#define CC 512
#define LL 64
#define HH 8
#define DD 64

__device__ float g_q[NQ * CC];
__device__ float g_k[MK * CC];
__device__ float g_v[MK * CC];
__device__ float g_attn[NQ * CC];
__device__ float g_aux_scratch[NQ * LL];
__device__ int   g_key_start[BB];

// ---------------------------------------------------------------------------
__global__ void key_start_kernel(const int* __restrict__ key_batch_cnt) {
    if (threadIdx.x == 0) {
        int s = 0;
        for (int b = 0; b < BB; b++) { g_key_start[b] = s; s += key_batch_cnt[b]; }
    }
}

// ---------------------------------------------------------------------------
// Double-buffered SGEMM (NT): C[r,c] = alpha * (sum_k A[r,k]*Bw[c,k] + bias[c])
// BM=BN=128, BK=16, 256 threads, 8x8 micro-tile, 2 CTAs/SM.
// ---------------------------------------------------------------------------
__device__ __forceinline__ void sgemm_body(
    const float* __restrict__ A, const float* __restrict__ Bw,
    const float* __restrict__ bias, float* __restrict__ C,
    int K, int N, int row0, int col0, float alpha)
{
    __shared__ __align__(16) float As[2][16][128];
    __shared__ __align__(16) float Bs[2][16][128];

    const int tid = threadIdx.x;
    const int tx  = tid & 15;
    const int ty  = tid >> 4;
    const int lr  = tid >> 2;          // 0..63
    const int lk  = (tid & 3) << 2;    // 0,4,8,12

    const float* Arow0 = &A[(size_t)(row0 + lr) * K + lk];
    const float* Arow1 = &A[(size_t)(row0 + lr + 64) * K + lk];
    const float* Brow0 = &Bw[(size_t)(col0 + lr) * K + lk];
    const float* Brow1 = &Bw[(size_t)(col0 + lr + 64) * K + lk];

    float acc[8][8];
#pragma unroll
    for (int i = 0; i < 8; i++)
#pragma unroll
        for (int j = 0; j < 8; j++) acc[i][j] = 0.0f;

    // prologue: load tile 0 into buffer 0
    {
        float4 a0 = *reinterpret_cast<const float4*>(Arow0);
        float4 a1 = *reinterpret_cast<const float4*>(Arow1);
        float4 b0 = *reinterpret_cast<const float4*>(Brow0);
        float4 b1 = *reinterpret_cast<const float4*>(Brow1);
        As[0][lk+0][lr] = a0.x; As[0][lk+1][lr] = a0.y; As[0][lk+2][lr] = a0.z; As[0][lk+3][lr] = a0.w;
        As[0][lk+0][lr+64] = a1.x; As[0][lk+1][lr+64] = a1.y; As[0][lk+2][lr+64] = a1.z; As[0][lk+3][lr+64] = a1.w;
        Bs[0][lk+0][lr] = b0.x; Bs[0][lk+1][lr] = b0.y; Bs[0][lk+2][lr] = b0.z; Bs[0][lk+3][lr] = b0.w;
        Bs[0][lk+0][lr+64] = b1.x; Bs[0][lk+1][lr+64] = b1.y; Bs[0][lk+2][lr+64] = b1.z; Bs[0][lk+3][lr+64] = b1.w;
    }
    __syncthreads();

    int buf = 0;
    for (int k0 = 16; k0 < K; k0 += 16) {
        // prefetch next tile into registers
        float4 a0 = *reinterpret_cast<const float4*>(Arow0 + k0);
        float4 a1 = *reinterpret_cast<const float4*>(Arow1 + k0);
        float4 b0 = *reinterpret_cast<const float4*>(Brow0 + k0);
        float4 b1 = *reinterpret_cast<const float4*>(Brow1 + k0);

#pragma unroll
        for (int k = 0; k < 16; k++) {
            float4 x0 = *reinterpret_cast<const float4*>(&As[buf][k][ty * 8]);
            float4 x1 = *reinterpret_cast<const float4*>(&As[buf][k][ty * 8 + 4]);
            float4 y0 = *reinterpret_cast<const float4*>(&Bs[buf][k][tx * 8]);
            float4 y1 = *reinterpret_cast<const float4*>(&Bs[buf][k][tx * 8 + 4]);
            float ar[8] = {x0.x, x0.y, x0.z, x0.w, x1.x, x1.y, x1.z, x1.w};
            float br[8] = {y0.x, y0.y, y0.z, y0.w, y1.x, y1.y, y1.z, y1.w};
#pragma unroll
            for (int i = 0; i < 8; i++)
#pragma unroll
                for (int j = 0; j < 8; j++)
                    acc[i][j] = fmaf(ar[i], br[j], acc[i][j]);
        }

        int nb = buf ^ 1;
        As[nb][lk+0][lr] = a0.x; As[nb][lk+1][lr] = a0.y; As[nb][lk+2][lr] = a0.z; As[nb][lk+3][lr] = a0.w;
        As[nb][lk+0][lr+64] = a1.x; As[nb][lk+1][lr+64] = a1.y; As[nb][lk+2][lr+64] = a1.z; As[nb][lk+3][lr+64] = a1.w;
        Bs[nb][lk+0][lr] = b0.x; Bs[nb][lk+1][lr] = b0.y; Bs[nb][lk+2][lr] = b0.z; Bs[nb][lk+3][lr] = b0.w;
        Bs[nb][lk+0][lr+64] = b1.x; Bs[nb][lk+1][lr+64] = b1.y; Bs[nb][lk+2][lr+64] = b1.z; Bs[nb][lk+3][lr+64] = b1.w;
        __syncthreads();
        buf = nb;
    }

    // epilogue compute on last buffer
#pragma unroll
    for (int k = 0; k < 16; k++) {
        float4 x0 = *reinterpret_cast<const float4*>(&As[buf][k][ty * 8]);
        float4 x1 = *reinterpret_cast<const float4*>(&As[buf][k][ty * 8 + 4]);
        float4 y0 = *reinterpret_cast<const float4*>(&Bs[buf][k][tx * 8]);
        float4 y1 = *reinterpret_cast<const float4*>(&Bs[buf][k][tx * 8 + 4]);
        float ar[8] = {x0.x, x0.y, x0.z, x0.w, x1.x, x1.y, x1.z, x1.w};
        float br[8] = {y0.x, y0.y, y0.z, y0.w, y1.x, y1.y, y1.z, y1.w};
#pragma unroll
        for (int i = 0; i < 8; i++)
#pragma unroll
            for (int j = 0; j < 8; j++)
                acc[i][j] = fmaf(ar[i], br[j], acc[i][j]);
    }

    float breg[8];
#pragma unroll
    for (int j = 0; j < 8; j++) breg[j] = bias[col0 + tx * 8 + j];

#pragma unroll
    for (int i = 0; i < 8; i++) {
        size_t r = (size_t)(row0 + ty * 8 + i);
        float4 o0, o1;
        o0.x = alpha * (acc[i][0] + breg[0]);
        o0.y = alpha * (acc[i][1] + breg[1]);
        o0.z = alpha * (acc[i][2] + breg[2]);
        o0.w = alpha * (acc[i][3] + breg[3]);
        o1.x = alpha * (acc[i][4] + breg[4]);
        o1.y = alpha * (acc[i][5] + breg[5]);
        o1.z = alpha * (acc[i][6] + breg[6]);
        o1.w = alpha * (acc[i][7] + breg[7]);
        *reinterpret_cast<float4*>(&C[r * N + col0 + tx * 8])     = o0;
        *reinterpret_cast<float4*>(&C[r * N + col0 + tx * 8 + 4]) = o1;
    }
}

// Fused q/k/v projections: blockIdx.z selects which projection.
__global__ void __launch_bounds__(256, 2) proj3_kernel(
    const float* __restrict__ query, const float* __restrict__ key,
    const float* __restrict__ value, const float* __restrict__ Win,
    const float* __restrict__ bin)
{
    const int z = blockIdx.z;
    const float* A = (z == 0) ? query : (z == 1) ? key : value;
    float* Cout = (z == 0) ? g_q : (z == 1) ? g_k : g_v;
    const float alpha = (z == 0) ? 0.125f : 1.0f;
    sgemm_body(A, Win + (size_t)z * CC * CC, bin + z * CC, Cout,
               CC, CC, blockIdx.y * 128, blockIdx.x * 128, alpha);
}

__global__ void __launch_bounds__(256, 2) outproj_kernel(
    const float* __restrict__ Wout, const float* __restrict__ bout,
    float* __restrict__ out)
{
    sgemm_body(g_attn, Wout, bout, out, CC, CC,
               blockIdx.y * 128, blockIdx.x * 128, 1.0f);
}

// ---------------------------------------------------------------------------
// Gather attention, one block (4 warps) per query.
// Score phase: one warp per k-row, coalesced 512B loads + shuffle reduce.
// ---------------------------------------------------------------------------
__global__ void __launch_bounds__(128) attn_kernel(
    const int* __restrict__ index_pair,
    const int* __restrict__ index_pair_batch,
    float* __restrict__ aux_out)
{
    __shared__ __align__(16) float sq[CC];
    __shared__ float sw[LL * HH];
    __shared__ int   sg[LL];

    const int n = blockIdx.x;
    const int t = threadIdx.x;
    const int warp = t >> 5;
    const int lane = t & 31;

    *reinterpret_cast<float4*>(&sq[t * 4]) =
        *reinterpret_cast<const float4*>(&g_q[(size_t)n * CC + t * 4]);

    if (t < LL) {
        int raw = index_pair[n * LL + t];
        int b   = index_pair_batch[n];
        sg[t] = (raw >= 0) ? (raw + g_key_start[b]) : -1;
    }
    __syncthreads();

    // ---- scores: warp w handles rows l = w*16 .. w*16+15 ----
    const float4* sq4 = reinterpret_cast<const float4*>(sq);
#pragma unroll 1
    for (int li = 0; li < 16; li++) {
        int l = warp * 16 + li;
        int g = sg[l];
        if (g < 0) {
            if (lane < 8) sw[l * 8 + lane] = -1000.0f;
            continue;
        }
        const float4* kr = reinterpret_cast<const float4*>(&g_k[(size_t)g * CC]);
#pragma unroll
        for (int p = 0; p < 4; p++) {
            float4 kv = kr[p * 32 + lane];
            float4 q4 = sq4[p * 32 + lane];
            float s = kv.x * q4.x + kv.y * q4.y + kv.z * q4.z + kv.w * q4.w;
            // reduce within 16-lane groups (two heads per pass)
            s += __shfl_xor_sync(0xffffffffu, s, 1);
            s += __shfl_xor_sync(0xffffffffu, s, 2);
            s += __shfl_xor_sync(0xffffffffu, s, 4);
            s += __shfl_xor_sync(0xffffffffu, s, 8);
            if ((lane & 15) == 0)
                sw[l * 8 + 2 * p + (lane >> 4)] = s;
        }
    }
    __syncthreads();

    // ---- softmax over l per head: 16 threads per head ----
    {
        int h = t >> 4, j = t & 15;
        float vals[4];
        float m = -1e30f;
#pragma unroll
        for (int i = 0; i < 4; i++) {
            vals[i] = sw[(j + 16 * i) * 8 + h];
            m = fmaxf(m, vals[i]);
        }
#pragma unroll
        for (int off = 8; off; off >>= 1)
            m = fmaxf(m, __shfl_xor_sync(0xffffffffu, m, off, 16));
        float s = 0.0f;
#pragma unroll
        for (int i = 0; i < 4; i++) { vals[i] = expf(vals[i] - m); s += vals[i]; }
#pragma unroll
        for (int off = 8; off; off >>= 1)
            s += __shfl_xor_sync(0xffffffffu, s, off, 16);
        float inv = 1.0f / s;
#pragma unroll
        for (int i = 0; i < 4; i++)
            sw[(j + 16 * i) * 8 + h] = vals[i] * inv;
    }
    __syncthreads();

    // ---- aux: mean over heads ----
    if (t < LL) {
        float s = 0.0f;
#pragma unroll
        for (int h = 0; h < 8; h++) s += sw[t * 8 + h];
        aux_out[(size_t)n * LL + t] = s * 0.125f;
    }

    // ---- weighted sum: each thread owns one float4 of output ----
    {
        int h  = t >> 4;           // 0..7
        int d4 = t & 15;           // float4 index within head
        float4 acc = make_float4(0.f, 0.f, 0.f, 0.f);
        size_t coloff = (size_t)(h * DD + d4 * 4);
#pragma unroll 4
        for (int l = 0; l < LL; l++) {
            int g = sg[l];
            int gg = (g >= 0) ? g : 0;     // masked weight is exactly 0
            float w = sw[l * 8 + h];
            float4 v4 = *reinterpret_cast<const float4*>(&g_v[(size_t)gg * CC + coloff]);
            acc.x = fmaf(w, v4.x, acc.x);
            acc.y = fmaf(w, v4.y, acc.y);
            acc.z = fmaf(w, v4.z, acc.z);
            acc.w = fmaf(w, v4.w, acc.w);
        }
        *reinterpret_cast<float4*>(&g_attn[(size_t)n * CC + coloff]) = acc;
    }
}

// ---------------------------------------------------------------------------
extern "C" void kernel_launch(void* const* d_in, const int* in_sizes, int n_in,
                              void* d_out, int out_size) {
    const float* query  = (const float*)d_in[0];
    const float* key    = (const float*)d_in[1];
    const float* value  = (const float*)d_in[2];
    const float* Win    = (const float*)d_in[3];
    const float* bin    = (const float*)d_in[4];
    const float* Wout   = (const float*)d_in[5];
    const float* bout   = (const float*)d_in[6];
    const int*   index_pair       = (const int*)d_in[7];
    const int*   key_batch_cnt    = (const int*)d_in[9];
    const int*   index_pair_batch = (const int*)d_in[10];
    float* out = (float*)d_out;

    float* auxs;
    cudaGetSymbolAddress((void**)&auxs, g_aux_scratch);
    float* aux_out = (out_size >= NQ * CC + NQ * LL) ? (out + (size_t)NQ * CC) : auxs;

    key_start_kernel<<<1, 32>>>(key_batch_cnt);

    dim3 gproj(CC / 128, NQ / 128, 3);
    proj3_kernel<<<gproj, 256>>>(query, key, value, Win, bin);

    attn_kernel<<<NQ, 128>>>(index_pair, index_pair_batch, aux_out);

    dim3 gout(CC / 128, NQ / 128);
    outproj_kernel<<<gout, 256>>>(Wout, bout, out);
}